// round 5
// baseline (speedup 1.0000x reference)
#include <cuda_runtime.h>
#include <math.h>

#define B_SZ   8
#define N_TOK  4096
#define D_MOD  512
#define H_HD   8
#define DH_SZ  64
#define M_LM   256
#define BH_SZ  64
#define Q_SCALE 0.125f

#define SZ_QKV (BH_SZ * N_TOK * DH_SZ)
#define SZ_L   (BH_SZ * M_LM * DH_SZ)
#define SZ_M2  (BH_SZ * M_LM * M_LM)

// ---------------- scratch ---------------------------------------------------
__device__ float g_q[SZ_QKV];
__device__ float g_k[SZ_QKV];
__device__ float g_v[SZ_QKV];
__device__ float g_ql[SZ_L];
__device__ float g_kl[SZ_L];
__device__ float g_attn2[SZ_M2];
__device__ float g_za[SZ_M2];
__device__ float g_zb[SZ_M2];
__device__ float g_m1[SZ_M2];
__device__ float g_u[SZ_M2];
__device__ float g_w2[SZ_M2];
__device__ float g_av[SZ_L];
__device__ float g_Wz[SZ_L];
__device__ float g_attno[SZ_QKV];
__device__ float g_scal[2];
__device__ float g_pacc[BH_SZ * 8 * M_LM * DH_SZ];
__device__ float g_pms[BH_SZ * 8 * M_LM * 2];

// ---------------- tf32 / fragment helpers ----------------------------------
__device__ __forceinline__ float tf32r(float x)
{
    unsigned u;
    asm("cvt.rna.tf32.f32 %0, %1;" : "=r"(u) : "f"(x));
    return __uint_as_float(u);
}
__device__ __forceinline__ unsigned fu(float x) { return __float_as_uint(x); }

__device__ __forceinline__ void mma8(float* c, const unsigned* a, const unsigned* b)
{
    asm volatile(
        "mma.sync.aligned.m16n8k8.row.col.f32.tf32.tf32.f32 "
        "{%0,%1,%2,%3}, {%4,%5,%6,%7}, {%8,%9}, {%0,%1,%2,%3};"
        : "+f"(c[0]), "+f"(c[1]), "+f"(c[2]), "+f"(c[3])
        : "r"(a[0]), "r"(a[1]), "r"(a[2]), "r"(a[3]), "r"(b[0]), "r"(b[1]));
}

// fragment-major smem stores (mma.m16n8k8 tf32 layouts).
// A-frag: a0=(m=g,k=t4) a1=(m=g+8,k=t4) a2=(m=g,k=t4+4) a3=(m=g+8,k=t4+4)
// AsF[ks][mt][lane][4]
__device__ __forceinline__ void sts_af(float* AsF, int MT, int ks, int m,
                                       int kin, float v)
{
    int lane = (m & 7) * 4 + (kin & 3);
    int reg  = ((m >> 3) & 1) + 2 * (kin >> 2);
    AsF[((ks * MT + (m >> 4)) * 32 + lane) * 4 + reg] = v;
}
// B-frag: b0=(k=t4, n=g), b1=(k=t4+4, n=g)  ->  lane=(n&7)*4+(kin&3)
// BsF[ks][nt][lane][2]
__device__ __forceinline__ void sts_bf(float* BsF, int NT, int ks, int kin,
                                       int n, float v)
{
    int lane = (n & 7) * 4 + (kin & 3);
    BsF[((ks * NT + (n >> 3)) * 32 + lane) * 2 + (kin >> 2)] = v;
}

// ---------------- zero ------------------------------------------------------
__global__ void k_zero() { g_scal[0] = 0.f; g_scal[1] = 0.f; }

// ---------------- QKV projection (tf32 MMA, frag-major smem) ---------------
__global__ __launch_bounds__(256)
void k_qkv_tc(const float* __restrict__ X, const float* __restrict__ Wm)
{
    __shared__ float AsF[2 * 8 * 32 * 4];    // 2048: 128x16 A
    __shared__ float BsF[2 * 16 * 32 * 2];   // 2048: 16x128 B
    const int tid = threadIdx.x, lane = tid & 31, warp = tid >> 5;
    const int g = lane >> 2, t4 = lane & 3;
    const int bm = blockIdx.y * 128, bn = blockIdx.x * 128;
    const int mtb = (warp >> 1) * 2, ntb = (warp & 1) * 8;
    const int arow = tid >> 1, aq = (tid & 1) * 8, aks = aq >> 3;
    const int brow = tid >> 4, bq = (tid & 15) * 8;
    const int bks = brow >> 3, bkin = brow & 7;

    float acc[2][8][4] = {};
    const float* Arow = X + (size_t)(bm + arow) * 512;

    for (int k0 = 0; k0 < 512; k0 += 16) {
        float4 a4 = *(const float4*)(Arow + k0 + aq);
        float4 a5 = *(const float4*)(Arow + k0 + aq + 4);
        sts_af(AsF, 8, aks, arow, 0, tf32r(a4.x));
        sts_af(AsF, 8, aks, arow, 1, tf32r(a4.y));
        sts_af(AsF, 8, aks, arow, 2, tf32r(a4.z));
        sts_af(AsF, 8, aks, arow, 3, tf32r(a4.w));
        sts_af(AsF, 8, aks, arow, 4, tf32r(a5.x));
        sts_af(AsF, 8, aks, arow, 5, tf32r(a5.y));
        sts_af(AsF, 8, aks, arow, 6, tf32r(a5.z));
        sts_af(AsF, 8, aks, arow, 7, tf32r(a5.w));
        const float* Brow = Wm + (size_t)(k0 + brow) * 1536 + bn + bq;
        float4 b4 = *(const float4*)(Brow);
        float4 b5 = *(const float4*)(Brow + 4);
        sts_bf(BsF, 16, bks, bkin, bq + 0, tf32r(b4.x));
        sts_bf(BsF, 16, bks, bkin, bq + 1, tf32r(b4.y));
        sts_bf(BsF, 16, bks, bkin, bq + 2, tf32r(b4.z));
        sts_bf(BsF, 16, bks, bkin, bq + 3, tf32r(b4.w));
        sts_bf(BsF, 16, bks, bkin, bq + 4, tf32r(b5.x));
        sts_bf(BsF, 16, bks, bkin, bq + 5, tf32r(b5.y));
        sts_bf(BsF, 16, bks, bkin, bq + 6, tf32r(b5.z));
        sts_bf(BsF, 16, bks, bkin, bq + 7, tf32r(b5.w));
        __syncthreads();
#pragma unroll
        for (int ks = 0; ks < 2; ++ks) {
            float4 af0 = *(const float4*)&AsF[((ks * 8 + mtb) * 32 + lane) * 4];
            float4 af1 = *(const float4*)&AsF[((ks * 8 + mtb + 1) * 32 + lane) * 4];
#pragma unroll
            for (int nt = 0; nt < 8; ++nt) {
                float2 bf = *(const float2*)&BsF[((ks * 16 + ntb + nt) * 32 + lane) * 2];
                mma8(acc[0][nt], (const unsigned*)&af0, (const unsigned*)&bf);
                mma8(acc[1][nt], (const unsigned*)&af1, (const unsigned*)&bf);
            }
        }
        __syncthreads();
    }

    const int sec = bn >> 9;
    float* dst = (sec == 0) ? g_q : (sec == 1) ? g_k : g_v;
    const float scl = (sec == 0) ? Q_SCALE : 1.f;
#pragma unroll
    for (int mt = 0; mt < 2; ++mt) {
        int gr0 = bm + (mtb + mt) * 16 + g;
        int gr1 = gr0 + 8;
        int b0i = gr0 >> 12, n0i = gr0 & 4095;
        int b1i = gr1 >> 12, n1i = gr1 & 4095;
#pragma unroll
        for (int nt = 0; nt < 8; ++nt) {
            int gc = bn + (ntb + nt) * 8 + 2 * t4;
            int h = (gc >> 6) & 7, d = gc & 63;
            *(float2*)&dst[(((size_t)(b0i * 8 + h) * 4096) + n0i) * 64 + d] =
                make_float2(acc[mt][nt][0] * scl, acc[mt][nt][1] * scl);
            *(float2*)&dst[(((size_t)(b1i * 8 + h) * 4096) + n1i) * 64 + d] =
                make_float2(acc[mt][nt][2] * scl, acc[mt][nt][3] * scl);
        }
    }
}

// ---------------- landmark means --------------------------------------------
__global__ void k_landmark()
{
    int idx = blockIdx.x * 256 + threadIdx.x;
    int bh = idx >> 14;
    int rem = idx & 16383;
    int mm = rem >> 6, d = rem & 63;
    size_t base = ((size_t)bh * 4096 + mm * 16) * 64 + d;
    float sq = 0.f, sk = 0.f;
#pragma unroll
    for (int t = 0; t < 16; ++t) {
        sq += g_q[base + (size_t)t * 64];
        sk += g_k[base + (size_t)t * 64];
    }
    g_ql[idx] = sq * 0.0625f;
    g_kl[idx] = sk * 0.0625f;
}

// ---------------- av: tf32 MMA flash (frag-major), split-K ------------------
__global__ __launch_bounds__(256)
void attn_part_tc(const float* __restrict__ Q, const float* __restrict__ K,
                  const float* __restrict__ V)
{
    __shared__ float KsF[8 * 8 * 32 * 2];   // 4096
    __shared__ float VsF[8 * 8 * 32 * 2];   // 4096
    const int tid = threadIdx.x, lane = tid & 31, warp = tid >> 5;
    const int g = lane >> 2, t4 = lane & 3;
    const int bh = blockIdx.z, seg = blockIdx.y, q0 = blockIdx.x * 128;
    const int rowbase = warp * 16;

    const float* qb = Q + ((size_t)bh * 256 + q0 + rowbase) * 64;
    unsigned aq[8][4];
#pragma unroll
    for (int ks = 0; ks < 8; ++ks) {
        aq[ks][0] = fu(tf32r(qb[(size_t)g * 64 + ks * 8 + t4]));
        aq[ks][1] = fu(tf32r(qb[(size_t)(g + 8) * 64 + ks * 8 + t4]));
        aq[ks][2] = fu(tf32r(qb[(size_t)g * 64 + ks * 8 + t4 + 4]));
        aq[ks][3] = fu(tf32r(qb[(size_t)(g + 8) * 64 + ks * 8 + t4 + 4]));
    }

    float m0 = -1e30f, m1 = -1e30f, s0 = 0.f, s1 = 0.f;
    float po[8][4] = {};

    const float* Kp = K + ((size_t)bh * 4096 + seg * 512) * 64;
    const float* Vp = V + ((size_t)bh * 4096 + seg * 512) * 64;
    const int ldn = tid >> 2, ldk = (tid & 3) * 16;
    const int srcA = (g << 2) + (t4 >> 1);
    const int srcB = srcA + 2;
    const bool odd = (t4 & 1);

    for (int ch = 0; ch < 8; ++ch) {
        const float* ksrc = Kp + (size_t)(ch * 64 + ldn) * 64 + ldk;
        const float* vsrc = Vp + (size_t)(ch * 64 + ldn) * 64 + ldk;
#pragma unroll
        for (int i = 0; i < 16; i += 4) {
            int d = ldk + i;
            float4 kv = *(const float4*)(ksrc + i);
            sts_bf(KsF, 8, d >> 3, d & 7, ldn, tf32r(kv.x));
            sts_bf(KsF, 8, (d + 1) >> 3, (d + 1) & 7, ldn, tf32r(kv.y));
            sts_bf(KsF, 8, (d + 2) >> 3, (d + 2) & 7, ldn, tf32r(kv.z));
            sts_bf(KsF, 8, (d + 3) >> 3, (d + 3) & 7, ldn, tf32r(kv.w));
            float4 vv = *(const float4*)(vsrc + i);
            sts_bf(VsF, 8, ldn >> 3, ldn & 7, d, tf32r(vv.x));
            sts_bf(VsF, 8, ldn >> 3, ldn & 7, d + 1, tf32r(vv.y));
            sts_bf(VsF, 8, ldn >> 3, ldn & 7, d + 2, tf32r(vv.z));
            sts_bf(VsF, 8, ldn >> 3, ldn & 7, d + 3, tf32r(vv.w));
        }
        __syncthreads();

        float sc[8][4] = {};
#pragma unroll
        for (int ks = 0; ks < 8; ++ks) {
#pragma unroll
            for (int nt = 0; nt < 8; ++nt) {
                float2 bf = *(const float2*)&KsF[((ks * 8 + nt) * 32 + lane) * 2];
                mma8(sc[nt], aq[ks], (const unsigned*)&bf);
            }
        }

        float c0 = -1e30f, c1 = -1e30f;
#pragma unroll
        for (int nt = 0; nt < 8; ++nt) {
            c0 = fmaxf(c0, fmaxf(sc[nt][0], sc[nt][1]));
            c1 = fmaxf(c1, fmaxf(sc[nt][2], sc[nt][3]));
        }
        c0 = fmaxf(c0, __shfl_xor_sync(0xffffffff, c0, 1));
        c0 = fmaxf(c0, __shfl_xor_sync(0xffffffff, c0, 2));
        c1 = fmaxf(c1, __shfl_xor_sync(0xffffffff, c1, 1));
        c1 = fmaxf(c1, __shfl_xor_sync(0xffffffff, c1, 2));
        float nm0 = fmaxf(m0, c0), nm1 = fmaxf(m1, c1);
        float f0 = __expf(m0 - nm0), f1 = __expf(m1 - nm1);
        m0 = nm0; m1 = nm1;
        s0 *= f0; s1 *= f1;
#pragma unroll
        for (int nt = 0; nt < 8; ++nt) {
            po[nt][0] *= f0; po[nt][1] *= f0;
            po[nt][2] *= f1; po[nt][3] *= f1;
        }

        unsigned pt[8][4];
#pragma unroll
        for (int nt = 0; nt < 8; ++nt) {
            float p0 = __expf(sc[nt][0] - m0); s0 += p0;
            float p1 = __expf(sc[nt][1] - m0); s0 += p1;
            float p2 = __expf(sc[nt][2] - m1); s1 += p2;
            float p3 = __expf(sc[nt][3] - m1); s1 += p3;
            pt[nt][0] = fu(tf32r(p0));
            pt[nt][1] = fu(tf32r(p1));
            pt[nt][2] = fu(tf32r(p2));
            pt[nt][3] = fu(tf32r(p3));
        }

#pragma unroll
        for (int ks = 0; ks < 8; ++ks) {
            unsigned u00 = __shfl_sync(0xffffffff, pt[ks][0], srcA);
            unsigned u01 = __shfl_sync(0xffffffff, pt[ks][1], srcA);
            unsigned u10 = __shfl_sync(0xffffffff, pt[ks][2], srcA);
            unsigned u11 = __shfl_sync(0xffffffff, pt[ks][3], srcA);
            unsigned u20 = __shfl_sync(0xffffffff, pt[ks][0], srcB);
            unsigned u21 = __shfl_sync(0xffffffff, pt[ks][1], srcB);
            unsigned u30 = __shfl_sync(0xffffffff, pt[ks][2], srcB);
            unsigned u31 = __shfl_sync(0xffffffff, pt[ks][3], srcB);
            unsigned ap[4];
            ap[0] = odd ? u01 : u00;
            ap[1] = odd ? u11 : u10;
            ap[2] = odd ? u21 : u20;
            ap[3] = odd ? u31 : u30;
#pragma unroll
            for (int nt = 0; nt < 8; ++nt) {
                float2 bf = *(const float2*)&VsF[((ks * 8 + nt) * 32 + lane) * 2];
                mma8(po[nt], ap, (const unsigned*)&bf);
            }
        }
        __syncthreads();
    }

    s0 += __shfl_xor_sync(0xffffffff, s0, 1);
    s0 += __shfl_xor_sync(0xffffffff, s0, 2);
    s1 += __shfl_xor_sync(0xffffffff, s1, 1);
    s1 += __shfl_xor_sync(0xffffffff, s1, 2);

    int r0 = q0 + rowbase + g, r1 = r0 + 8;
    size_t idx0 = (size_t)(bh * 8 + seg) * 256 + r0;
    size_t idx1 = (size_t)(bh * 8 + seg) * 256 + r1;
    if (t4 == 0) {
        g_pms[idx0 * 2] = m0; g_pms[idx0 * 2 + 1] = s0;
        g_pms[idx1 * 2] = m1; g_pms[idx1 * 2 + 1] = s1;
    }
    float* o0 = g_pacc + idx0 * 64;
    float* o1 = g_pacc + idx1 * 64;
#pragma unroll
    for (int nt = 0; nt < 8; ++nt) {
        int col = nt * 8 + 2 * t4;
        *(float2*)&o0[col] = make_float2(po[nt][0], po[nt][1]);
        *(float2*)&o1[col] = make_float2(po[nt][2], po[nt][3]);
    }
}

__global__ void k_avmerge()
{
    const int r = blockIdx.x;
    const int bh = r >> 8, q = r & 255;
    const int d = threadIdx.x;
    float ms[8];
    float M = -1e30f;
#pragma unroll
    for (int s = 0; s < 8; ++s) {
        ms[s] = g_pms[(((size_t)bh * 8 + s) * 256 + q) * 2];
        M = fmaxf(M, ms[s]);
    }
    float denom = 0.f, acc = 0.f;
#pragma unroll
    for (int s = 0; s < 8; ++s) {
        size_t idx = ((size_t)bh * 8 + s) * 256 + q;
        float w = __expf(ms[s] - M);
        denom += g_pms[idx * 2 + 1] * w;
        acc += g_pacc[idx * 64 + d] * w;
    }
    g_av[((size_t)bh * 256 + q) * 64 + d] = acc / denom;
}

// ---------------- attn1: softmax(q@kl^T)@W, direct (frag-major flash) -------
__global__ __launch_bounds__(256)
void attn_direct_tc(const float* __restrict__ Q, const float* __restrict__ K,
                    const float* __restrict__ V, float* __restrict__ O)
{
    __shared__ float KsF[8 * 8 * 32 * 2];
    __shared__ float VsF[8 * 8 * 32 * 2];
    const int tid = threadIdx.x, lane = tid & 31, warp = tid >> 5;
    const int g = lane >> 2, t4 = lane & 3;
    const int bh = blockIdx.y, q0 = blockIdx.x * 128;
    const int rowbase = warp * 16;

    const float* qb = Q + ((size_t)bh * 4096 + q0 + rowbase) * 64;
    unsigned aq[8][4];
#pragma unroll
    for (int ks = 0; ks < 8; ++ks) {
        aq[ks][0] = fu(tf32r(qb[(size_t)g * 64 + ks * 8 + t4]));
        aq[ks][1] = fu(tf32r(qb[(size_t)(g + 8) * 64 + ks * 8 + t4]));
        aq[ks][2] = fu(tf32r(qb[(size_t)g * 64 + ks * 8 + t4 + 4]));
        aq[ks][3] = fu(tf32r(qb[(size_t)(g + 8) * 64 + ks * 8 + t4 + 4]));
    }

    float m0 = -1e30f, m1 = -1e30f, s0 = 0.f, s1 = 0.f;
    float po[8][4] = {};

    const float* Kp = K + (size_t)bh * 256 * 64;
    const float* Vp = V + (size_t)bh * 256 * 64;
    const int ldn = tid >> 2, ldk = (tid & 3) * 16;
    const int srcA = (g << 2) + (t4 >> 1);
    const int srcB = srcA + 2;
    const bool odd = (t4 & 1);

    for (int ch = 0; ch < 4; ++ch) {
        const float* ksrc = Kp + (size_t)(ch * 64 + ldn) * 64 + ldk;
        const float* vsrc = Vp + (size_t)(ch * 64 + ldn) * 64 + ldk;
#pragma unroll
        for (int i = 0; i < 16; i += 4) {
            int d = ldk + i;
            float4 kv = *(const float4*)(ksrc + i);
            sts_bf(KsF, 8, d >> 3, d & 7, ldn, tf32r(kv.x));
            sts_bf(KsF, 8, (d + 1) >> 3, (d + 1) & 7, ldn, tf32r(kv.y));
            sts_bf(KsF, 8, (d + 2) >> 3, (d + 2) & 7, ldn, tf32r(kv.z));
            sts_bf(KsF, 8, (d + 3) >> 3, (d + 3) & 7, ldn, tf32r(kv.w));
            float4 vv = *(const float4*)(vsrc + i);
            sts_bf(VsF, 8, ldn >> 3, ldn & 7, d, tf32r(vv.x));
            sts_bf(VsF, 8, ldn >> 3, ldn & 7, d + 1, tf32r(vv.y));
            sts_bf(VsF, 8, ldn >> 3, ldn & 7, d + 2, tf32r(vv.z));
            sts_bf(VsF, 8, ldn >> 3, ldn & 7, d + 3, tf32r(vv.w));
        }
        __syncthreads();

        float sc[8][4] = {};
#pragma unroll
        for (int ks = 0; ks < 8; ++ks) {
#pragma unroll
            for (int nt = 0; nt < 8; ++nt) {
                float2 bf = *(const float2*)&KsF[((ks * 8 + nt) * 32 + lane) * 2];
                mma8(sc[nt], aq[ks], (const unsigned*)&bf);
            }
        }

        float c0 = -1e30f, c1 = -1e30f;
#pragma unroll
        for (int nt = 0; nt < 8; ++nt) {
            c0 = fmaxf(c0, fmaxf(sc[nt][0], sc[nt][1]));
            c1 = fmaxf(c1, fmaxf(sc[nt][2], sc[nt][3]));
        }
        c0 = fmaxf(c0, __shfl_xor_sync(0xffffffff, c0, 1));
        c0 = fmaxf(c0, __shfl_xor_sync(0xffffffff, c0, 2));
        c1 = fmaxf(c1, __shfl_xor_sync(0xffffffff, c1, 1));
        c1 = fmaxf(c1, __shfl_xor_sync(0xffffffff, c1, 2));
        float nm0 = fmaxf(m0, c0), nm1 = fmaxf(m1, c1);
        float f0 = __expf(m0 - nm0), f1 = __expf(m1 - nm1);
        m0 = nm0; m1 = nm1;
        s0 *= f0; s1 *= f1;
#pragma unroll
        for (int nt = 0; nt < 8; ++nt) {
            po[nt][0] *= f0; po[nt][1] *= f0;
            po[nt][2] *= f1; po[nt][3] *= f1;
        }

        unsigned pt[8][4];
#pragma unroll
        for (int nt = 0; nt < 8; ++nt) {
            float p0 = __expf(sc[nt][0] - m0); s0 += p0;
            float p1 = __expf(sc[nt][1] - m0); s0 += p1;
            float p2 = __expf(sc[nt][2] - m1); s1 += p2;
            float p3 = __expf(sc[nt][3] - m1); s1 += p3;
            pt[nt][0] = fu(tf32r(p0));
            pt[nt][1] = fu(tf32r(p1));
            pt[nt][2] = fu(tf32r(p2));
            pt[nt][3] = fu(tf32r(p3));
        }

#pragma unroll
        for (int ks = 0; ks < 8; ++ks) {
            unsigned u00 = __shfl_sync(0xffffffff, pt[ks][0], srcA);
            unsigned u01 = __shfl_sync(0xffffffff, pt[ks][1], srcA);
            unsigned u10 = __shfl_sync(0xffffffff, pt[ks][2], srcA);
            unsigned u11 = __shfl_sync(0xffffffff, pt[ks][3], srcA);
            unsigned u20 = __shfl_sync(0xffffffff, pt[ks][0], srcB);
            unsigned u21 = __shfl_sync(0xffffffff, pt[ks][1], srcB);
            unsigned u30 = __shfl_sync(0xffffffff, pt[ks][2], srcB);
            unsigned u31 = __shfl_sync(0xffffffff, pt[ks][3], srcB);
            unsigned ap[4];
            ap[0] = odd ? u01 : u00;
            ap[1] = odd ? u11 : u10;
            ap[2] = odd ? u21 : u20;
            ap[3] = odd ? u31 : u30;
#pragma unroll
            for (int nt = 0; nt < 8; ++nt) {
                float2 bf = *(const float2*)&VsF[((ks * 8 + nt) * 32 + lane) * 2];
                mma8(po[nt], ap, (const unsigned*)&bf);
            }
        }
        __syncthreads();
    }

    s0 += __shfl_xor_sync(0xffffffff, s0, 1);
    s0 += __shfl_xor_sync(0xffffffff, s0, 2);
    s1 += __shfl_xor_sync(0xffffffff, s1, 1);
    s1 += __shfl_xor_sync(0xffffffff, s1, 2);
    float inv0 = 1.f / s0, inv1 = 1.f / s1;

    int r0 = q0 + rowbase + g, r1 = r0 + 8;
    float* o0 = O + ((size_t)bh * 4096 + r0) * 64;
    float* o1 = O + ((size_t)bh * 4096 + r1) * 64;
#pragma unroll
    for (int nt = 0; nt < 8; ++nt) {
        int col = nt * 8 + 2 * t4;
        *(float2*)&o0[col] = make_float2(po[nt][0] * inv0, po[nt][1] * inv0);
        *(float2*)&o1[col] = make_float2(po[nt][2] * inv1, po[nt][3] * inv1);
    }
}

// ---------------- fused sim2 + softmax (frag-major tf32) --------------------
__global__ __launch_bounds__(256)
void k_sim2sm()
{
    __shared__ float BF[8 * 8 * 32 * 2];
    const int tid = threadIdx.x, lane = tid & 31, warp = tid >> 5;
    const int g = lane >> 2, t4 = lane & 3;
    const int bh = blockIdx.y, q0 = blockIdx.x * 128;
    const int rowbase = warp * 16;

    const float* qb = g_ql + ((size_t)bh * 256 + q0 + rowbase) * 64;
    unsigned aq[8][4];
#pragma unroll
    for (int ks = 0; ks < 8; ++ks) {
        aq[ks][0] = fu(tf32r(qb[(size_t)g * 64 + ks * 8 + t4]));
        aq[ks][1] = fu(tf32r(qb[(size_t)(g + 8) * 64 + ks * 8 + t4]));
        aq[ks][2] = fu(tf32r(qb[(size_t)g * 64 + ks * 8 + t4 + 4]));
        aq[ks][3] = fu(tf32r(qb[(size_t)(g + 8) * 64 + ks * 8 + t4 + 4]));
    }

    float acc1[32][4] = {};
    const float* klb = g_kl + (size_t)bh * 256 * 64;
    const int ldn = tid >> 2, ldk = (tid & 3) * 16;
    for (int c = 0; c < 4; ++c) {
        const float* src = klb + (size_t)(c * 64 + ldn) * 64 + ldk;
#pragma unroll
        for (int i = 0; i < 16; i += 4) {
            int d = ldk + i;
            float4 v = *(const float4*)(src + i);
            sts_bf(BF, 8, d >> 3, d & 7, ldn, tf32r(v.x));
            sts_bf(BF, 8, (d + 1) >> 3, (d + 1) & 7, ldn, tf32r(v.y));
            sts_bf(BF, 8, (d + 2) >> 3, (d + 2) & 7, ldn, tf32r(v.z));
            sts_bf(BF, 8, (d + 3) >> 3, (d + 3) & 7, ldn, tf32r(v.w));
        }
        __syncthreads();
#pragma unroll
        for (int ks = 0; ks < 8; ++ks) {
#pragma unroll
            for (int nt = 0; nt < 8; ++nt) {
                float2 bf = *(const float2*)&BF[((ks * 8 + nt) * 32 + lane) * 2];
                mma8(acc1[c * 8 + nt], aq[ks], (const unsigned*)&bf);
            }
        }
        __syncthreads();
    }

    float m0v = -1e30f, m1v = -1e30f;
#pragma unroll
    for (int nt = 0; nt < 32; ++nt) {
        m0v = fmaxf(m0v, fmaxf(acc1[nt][0], acc1[nt][1]));
        m1v = fmaxf(m1v, fmaxf(acc1[nt][2], acc1[nt][3]));
    }
    m0v = fmaxf(m0v, __shfl_xor_sync(0xffffffff, m0v, 1));
    m0v = fmaxf(m0v, __shfl_xor_sync(0xffffffff, m0v, 2));
    m1v = fmaxf(m1v, __shfl_xor_sync(0xffffffff, m1v, 1));
    m1v = fmaxf(m1v, __shfl_xor_sync(0xffffffff, m1v, 2));
    float s0 = 0.f, s1 = 0.f;
#pragma unroll
    for (int nt = 0; nt < 32; ++nt) {
        acc1[nt][0] = __expf(acc1[nt][0] - m0v);
        acc1[nt][1] = __expf(acc1[nt][1] - m0v);
        acc1[nt][2] = __expf(acc1[nt][2] - m1v);
        acc1[nt][3] = __expf(acc1[nt][3] - m1v);
        s0 += acc1[nt][0] + acc1[nt][1];
        s1 += acc1[nt][2] + acc1[nt][3];
    }
    s0 += __shfl_xor_sync(0xffffffff, s0, 1);
    s0 += __shfl_xor_sync(0xffffffff, s0, 2);
    s1 += __shfl_xor_sync(0xffffffff, s1, 1);
    s1 += __shfl_xor_sync(0xffffffff, s1, 2);
    float inv0 = 1.f / s0, inv1 = 1.f / s1;

    int r0 = q0 + rowbase + g, r1 = r0 + 8;
    float* row0 = g_attn2 + (size_t)bh * 65536 + (size_t)r0 * 256;
    float* row1 = g_attn2 + (size_t)bh * 65536 + (size_t)r1 * 256;
#pragma unroll
    for (int nt = 0; nt < 32; ++nt) {
        int col = nt * 8 + 2 * t4;
        *(float2*)&row0[col] = make_float2(acc1[nt][0] * inv0, acc1[nt][1] * inv0);
        *(float2*)&row1[col] = make_float2(acc1[nt][2] * inv1, acc1[nt][3] * inv1);
    }
}

// ---------------- pinv scalars ----------------------------------------------
__global__ void k_scal()
{
    __shared__ float s1[256], s2[256];
    const int tid = threadIdx.x;
    const float* x = g_attn2 + (size_t)blockIdx.x * 65536;
    float cs = 0.f, rs = 0.f;
    for (int i = 0; i < 256; ++i) cs += fabsf(x[i * 256 + tid]);
    for (int j = 0; j < 256; ++j) rs += fabsf(x[tid * 256 + j]);
    s1[tid] = rs; s2[tid] = cs;
    __syncthreads();
    for (int s = 128; s > 0; s >>= 1) {
        if (tid < s) {
            s1[tid] = fmaxf(s1[tid], s1[tid + s]);
            s2[tid] = fmaxf(s2[tid], s2[tid + s]);
        }
        __syncthreads();
    }
    if (tid == 0) {
        atomicMax((int*)&g_scal[0], __float_as_int(s1[0]));
        atomicMax((int*)&g_scal[1], __float_as_int(s2[0]));
    }
}

__global__ void k_initz()
{
    int idx = blockIdx.x * 256 + threadIdx.x;
    float inv = 1.f / (g_scal[0] * g_scal[1]);
    int bh = idx >> 16, r = (idx >> 8) & 255, c = idx & 255;
    g_za[idx] = g_attn2[((size_t)bh << 16) + (c << 8) + r] * inv;
}

// ---------------- batched 256^3 tf32 GEMM, frag-major, 128x64 tiles ---------
__global__ __launch_bounds__(256)
void k_bgemm_tc(const float* __restrict__ A, const float* __restrict__ B,
                const float* __restrict__ S, float* __restrict__ D,
                float c0, float c1)
{
    const int bh = blockIdx.z;
    A += (size_t)bh * 65536; B += (size_t)bh * 65536;
    S += (size_t)bh * 65536; D += (size_t)bh * 65536;

    __shared__ float AsF[2 * 8 * 32 * 4];   // 2048
    __shared__ float BsF[2 * 8 * 32 * 2];   // 1024
    const int tid = threadIdx.x, lane = tid & 31, warp = tid >> 5;
    const int g = lane >> 2, t4 = lane & 3;
    const int m0 = blockIdx.y * 128, n0 = blockIdx.x * 64;
    const int mtb = (warp >> 1) * 2, ntb = (warp & 1) * 4;
    const int arow = tid >> 1, aq = (tid & 1) * 8, aks = aq >> 3;
    const int brow = tid >> 4, bq = (tid & 15) * 4;
    const int bks = brow >> 3, bkin = brow & 7;

    float acc[2][4][4] = {};
    const float* Arow = A + (size_t)(m0 + arow) * 256;

    for (int k0 = 0; k0 < 256; k0 += 16) {
        float4 a4 = *(const float4*)(Arow + k0 + aq);
        float4 a5 = *(const float4*)(Arow + k0 + aq + 4);
        sts_af(AsF, 8, aks, arow, 0, tf32r(a4.x));
        sts_af(AsF, 8, aks, arow, 1, tf32r(a4.y));
        sts_af(AsF, 8, aks, arow, 2, tf32r(a4.z));
        sts_af(AsF, 8, aks, arow, 3, tf32r(a4.w));
        sts_af(AsF, 8, aks, arow, 4, tf32r(a5.x));
        sts_af(AsF, 8, aks, arow, 5, tf32r(a5.y));
        sts_af(AsF, 8, aks, arow, 6, tf32r(a5.z));
        sts_af(AsF, 8, aks, arow, 7, tf32r(a5.w));
        float4 b4 = *(const float4*)(B + (size_t)(k0 + brow) * 256 + n0 + bq);
        sts_bf(BsF, 8, bks, bkin, bq + 0, tf32r(b4.x));
        sts_bf(BsF, 8, bks, bkin, bq + 1, tf32r(b4.y));
        sts_bf(BsF, 8, bks, bkin, bq + 2, tf32r(b4.z));
        sts_bf(BsF, 8, bks, bkin, bq + 3, tf32r(b4.w));
        __syncthreads();
#pragma unroll
        for (int ks = 0; ks < 2; ++ks) {
            float4 af0 = *(const float4*)&AsF[((ks * 8 + mtb) * 32 + lane) * 4];
            float4 af1 = *(const float4*)&AsF[((ks * 8 + mtb + 1) * 32 + lane) * 4];
#pragma unroll
            for (int nt = 0; nt < 4; ++nt) {
                float2 bf = *(const float2*)&BsF[((ks * 8 + ntb + nt) * 32 + lane) * 2];
                mma8(acc[0][nt], (const unsigned*)&af0, (const unsigned*)&bf);
                mma8(acc[1][nt], (const unsigned*)&af1, (const unsigned*)&bf);
            }
        }
        __syncthreads();
    }
#pragma unroll
    for (int mt = 0; mt < 2; ++mt) {
#pragma unroll
        for (int nt = 0; nt < 4; ++nt) {
            int gr0 = m0 + (mtb + mt) * 16 + g;
            int gc = n0 + (ntb + nt) * 8 + 2 * t4;
            size_t o0 = (size_t)gr0 * 256 + gc;
            size_t o1 = o0 + 8 * 256;
            float2 v0 = make_float2(c0 * acc[mt][nt][0], c0 * acc[mt][nt][1]);
            float2 v1 = make_float2(c0 * acc[mt][nt][2], c0 * acc[mt][nt][3]);
            if (c1 != 0.f) {
                float2 sv0 = *(const float2*)(S + o0);
                float2 sv1 = *(const float2*)(S + o1);
                v0.x += c1 * sv0.x; v0.y += c1 * sv0.y;
                v1.x += c1 * sv1.x; v1.y += c1 * sv1.y;
            }
            *(float2*)(D + o0) = v0;
            *(float2*)(D + o1) = v1;
        }
    }
}

// ---------------- W = z @ av (256x64x256, frag-major) -----------------------
__global__ __launch_bounds__(128)
void k_zw_tc(const float* __restrict__ Z, const float* __restrict__ AV,
             float* __restrict__ Wout)
{
    const int bh = blockIdx.z;
    Z += (size_t)bh * 65536; AV += (size_t)bh * 16384; Wout += (size_t)bh * 16384;

    __shared__ float AsF[2 * 8 * 32 * 4];
    __shared__ float BsF[2 * 8 * 32 * 2];
    const int tid = threadIdx.x, lane = tid & 31, warp = tid >> 5;
    const int g = lane >> 2, t4 = lane & 3;
    const int m0 = blockIdx.y * 128;
    const int mtb = warp * 2;
    const int brow = tid >> 3, bq = (tid & 7) * 8;
    const int bks = brow >> 3, bkin = brow & 7;

    float acc[2][8][4] = {};
    const float* Arow = Z + (size_t)(m0 + tid) * 256;

    for (int k0 = 0; k0 < 256; k0 += 16) {
#pragma unroll
        for (int i = 0; i < 16; i += 4) {
            float4 a4 = *(const float4*)(Arow + k0 + i);
            sts_af(AsF, 8, (i) >> 3, tid, (i) & 7, tf32r(a4.x));
            sts_af(AsF, 8, (i + 1) >> 3, tid, (i + 1) & 7, tf32r(a4.y));
            sts_af(AsF, 8, (i + 2) >> 3, tid, (i + 2) & 7, tf32r(a4.z));
            sts_af(AsF, 8, (i + 3) >> 3, tid, (i + 3) & 7, tf32r(a4.w));
        }
        const float* Brow = AV + (size_t)(k0 + brow) * 64 + bq;
        float4 b4 = *(const float4*)(Brow);
        float4 b5 = *(const float4*)(Brow + 4);
        sts_bf(BsF, 8, bks, bkin, bq + 0, tf32r(b4.x));
        sts_bf(BsF, 8, bks, bkin, bq + 1, tf32r(b4.y));
        sts_bf(BsF, 8, bks, bkin, bq + 2, tf32r(b4.z));
        sts_bf(BsF, 8, bks, bkin, bq + 3, tf32r(b4.w));
        sts_bf(BsF, 8, bks, bkin, bq + 4, tf32r(b5.x));
        sts_bf(BsF, 8, bks, bkin, bq + 5, tf32r(b5.y));
        sts_bf(BsF, 8, bks, bkin, bq + 6, tf32r(b5.z));
        sts_bf(BsF, 8, bks, bkin, bq + 7, tf32r(b5.w));
        __syncthreads();
#pragma unroll
        for (int ks = 0; ks < 2; ++ks) {
            float4 af0 = *(const float4*)&AsF[((ks * 8 + mtb) * 32 + lane) * 4];
            float4 af1 = *(const float4*)&AsF[((ks * 8 + mtb + 1) * 32 + lane) * 4];
#pragma unroll
            for (int nt = 0; nt < 8; ++nt) {
                float2 bf = *(const float2*)&BsF[((ks * 8 + nt) * 32 + lane) * 2];
                mma8(acc[0][nt], (const unsigned*)&af0, (const unsigned*)&bf);
                mma8(acc[1][nt], (const unsigned*)&af1, (const unsigned*)&bf);
            }
        }
        __syncthreads();
    }
#pragma unroll
    for (int mt = 0; mt < 2; ++mt) {
#pragma unroll
        for (int nt = 0; nt < 8; ++nt) {
            int gr0 = m0 + (mtb + mt) * 16 + g;
            int gc = nt * 8 + 2 * t4;
            *(float2*)&Wout[(size_t)gr0 * 64 + gc] =
                make_float2(acc[mt][nt][0], acc[mt][nt][1]);
            *(float2*)&Wout[(size_t)(gr0 + 8) * 64 + gc] =
                make_float2(acc[mt][nt][2], acc[mt][nt][3]);
        }
    }
}

// ---------------- output projection (frag-major tf32) -----------------------
__global__ __launch_bounds__(256)
void k_out_tc(const float* __restrict__ Wm, const float* __restrict__ bias,
              float* __restrict__ out)
{
    __shared__ float AsF[2 * 8 * 32 * 4];
    __shared__ float BsF[2 * 16 * 32 * 2];
    const int tid = threadIdx.x, lane = tid & 31, warp = tid >> 5;
    const int g = lane >> 2, t4 = lane & 3;
    const int bm = blockIdx.y * 128, bn = blockIdx.x * 128;
    const int mtb = (warp >> 1) * 2, ntb = (warp & 1) * 8;
    const int arow = tid >> 1, aq = (tid & 1) * 8, aks = aq >> 3;
    const int brow = tid >> 4, bq = (tid & 15) * 8;
    const int bks = brow >> 3, bkin = brow & 7;

    const int gr_a = bm + arow;
    const int b_a = gr_a >> 12, n_a = gr_a & 4095;

    float acc[2][8][4] = {};

    for (int k0 = 0; k0 < 512; k0 += 16) {
        int kk = k0 + aq;
        int h = kk >> 6, d = kk & 63;
        const float* ap = g_attno + (((size_t)(b_a * 8 + h) * 4096) + n_a) * 64 + d;
        float4 a4 = *(const float4*)(ap);
        float4 a5 = *(const float4*)(ap + 4);
        sts_af(AsF, 8, aks, arow, 0, tf32r(a4.x));
        sts_af(AsF, 8, aks, arow, 1, tf32r(a4.y));
        sts_af(AsF, 8, aks, arow, 2, tf32r(a4.z));
        sts_af(AsF, 8, aks, arow, 3, tf32r(a4.w));
        sts_af(AsF, 8, aks, arow, 4, tf32r(a5.x));
        sts_af(AsF, 8, aks, arow, 5, tf32r(a5.y));
        sts_af(AsF, 8, aks, arow, 6, tf32r(a5.z));
        sts_af(AsF, 8, aks, arow, 7, tf32r(a5.w));
        const float* Brow = Wm + (size_t)(k0 + brow) * 512 + bn + bq;
        float4 b4 = *(const float4*)(Brow);
        float4 b5 = *(const float4*)(Brow + 4);
        sts_bf(BsF, 16, bks, bkin, bq + 0, tf32r(b4.x));
        sts_bf(BsF, 16, bks, bkin, bq + 1, tf32r(b4.y));
        sts_bf(BsF, 16, bks, bkin, bq + 2, tf32r(b4.z));
        sts_bf(BsF, 16, bks, bkin, bq + 3, tf32r(b4.w));
        sts_bf(BsF, 16, bks, bkin, bq + 4, tf32r(b5.x));
        sts_bf(BsF, 16, bks, bkin, bq + 5, tf32r(b5.y));
        sts_bf(BsF, 16, bks, bkin, bq + 6, tf32r(b5.z));
        sts_bf(BsF, 16, bks, bkin, bq + 7, tf32r(b5.w));
        __syncthreads();
#pragma unroll
        for (int ks = 0; ks < 2; ++ks) {
            float4 af0 = *(const float4*)&AsF[((ks * 8 + mtb) * 32 + lane) * 4];
            float4 af1 = *(const float4*)&AsF[((ks * 8 + mtb + 1) * 32 + lane) * 4];
#pragma unroll
            for (int nt = 0; nt < 8; ++nt) {
                float2 bf = *(const float2*)&BsF[((ks * 16 + ntb + nt) * 32 + lane) * 2];
                mma8(acc[0][nt], (const unsigned*)&af0, (const unsigned*)&bf);
                mma8(acc[1][nt], (const unsigned*)&af1, (const unsigned*)&bf);
            }
        }
        __syncthreads();
    }
#pragma unroll
    for (int mt = 0; mt < 2; ++mt) {
#pragma unroll
        for (int nt = 0; nt < 8; ++nt) {
            int gr0 = bm + (mtb + mt) * 16 + g;
            int gc = bn + (ntb + nt) * 8 + 2 * t4;
            float bx = bias[gc], by = bias[gc + 1];
            *(float2*)&out[(size_t)gr0 * 512 + gc] =
                make_float2(acc[mt][nt][0] + bx, acc[mt][nt][1] + by);
            *(float2*)&out[(size_t)(gr0 + 8) * 512 + gc] =
                make_float2(acc[mt][nt][2] + bx, acc[mt][nt][3] + by);
        }
    }
}

// ---------------- launch ----------------------------------------------------
extern "C" void kernel_launch(void* const* d_in, const int* in_sizes, int n_in,
                              void* d_out, int out_size)
{
    const float* x     = (const float*)d_in[0];
    const float* w_qkv = (const float*)d_in[1];
    const float* w_out = (const float*)d_in[2];
    const float* b_out = (const float*)d_in[3];
    float* out = (float*)d_out;

    float *p_q, *p_k, *p_v, *p_ql, *p_kl, *p_attn2;
    float *p_za, *p_zb, *p_m1, *p_u, *p_w2, *p_av, *p_Wz, *p_ao;
    cudaGetSymbolAddress((void**)&p_q,     g_q);
    cudaGetSymbolAddress((void**)&p_k,     g_k);
    cudaGetSymbolAddress((void**)&p_v,     g_v);
    cudaGetSymbolAddress((void**)&p_ql,    g_ql);
    cudaGetSymbolAddress((void**)&p_kl,    g_kl);
    cudaGetSymbolAddress((void**)&p_attn2, g_attn2);
    cudaGetSymbolAddress((void**)&p_za,    g_za);
    cudaGetSymbolAddress((void**)&p_zb,    g_zb);
    cudaGetSymbolAddress((void**)&p_m1,    g_m1);
    cudaGetSymbolAddress((void**)&p_u,     g_u);
    cudaGetSymbolAddress((void**)&p_w2,    g_w2);
    cudaGetSymbolAddress((void**)&p_av,    g_av);
    cudaGetSymbolAddress((void**)&p_Wz,    g_Wz);
    cudaGetSymbolAddress((void**)&p_ao,    g_attno);

    k_zero<<<1, 1>>>();
    k_qkv_tc<<<dim3(12, 256), 256>>>(x, w_qkv);
    k_landmark<<<4096, 256>>>();

    // 4th launch -> ncu capture slot (compare vs R3's 202us)
    attn_part_tc<<<dim3(2, 8, BH_SZ), 256>>>(p_ql, p_k, p_v);

    k_sim2sm<<<dim3(2, BH_SZ), 256>>>();
    k_avmerge<<<BH_SZ * M_LM, 64>>>();
    k_scal<<<BH_SZ, 256>>>();
    k_initz<<<16384, 256>>>();
    {
        float* za = p_za;
        float* zb = p_zb;
        dim3 gg(4, 2, BH_SZ);
        for (int it = 0; it < 6; ++it) {
            k_bgemm_tc<<<gg, 256>>>(p_attn2, za, za, p_m1, 1.f, 0.f);
            k_bgemm_tc<<<gg, 256>>>(p_m1, p_m1, p_m1, p_u, -1.f, 7.f);
            k_bgemm_tc<<<gg, 256>>>(p_m1, p_u, p_m1, p_w2, -1.f, 15.f);
            k_bgemm_tc<<<gg, 256>>>(za, p_w2, za, zb, -0.25f, 3.25f);
            float* t = za; za = zb; zb = t;
        }
        k_zw_tc<<<dim3(1, 2, BH_SZ), 128>>>(za, p_av, p_Wz);
    }

    attn_direct_tc<<<dim3(32, BH_SZ), 256>>>(p_q, p_kl, p_Wz, p_ao);
    k_out_tc<<<dim3(4, 256), 256>>>(w_out, b_out, out);
}